// round 1
// baseline (speedup 1.0000x reference)
#include <cuda_runtime.h>
#include <cstdint>

#define SEQ 2048
#define NB 2
#define ROWS (NB * SEQ)      // 4096 total (b,s) rows
#define HDIM 4096
#define NH 32
#define NKV 8
#define HD 128
#define QLD (NH * HD)        // 4096
#define KLD (NKV * HD)       // 1024
#define NBH (NB * NH)        // 64

// ---------------- scratch (static device allocations; no cudaMalloc) -------
__device__ float g_q[(size_t)ROWS * QLD];                 // 64 MB
__device__ float g_k[(size_t)ROWS * KLD];                 // 16 MB
__device__ float g_v[(size_t)ROWS * KLD];                 // 16 MB
__device__ float g_attn[(size_t)ROWS * QLD];              // 64 MB
__device__ float g_scores[(size_t)NBH * SEQ * SEQ];       // 1 GiB (scores -> probs in place)

// ---------------- tf32 mma GEMM core ---------------------------------------
#define BM 128
#define BN 128
#define BK 16
#define SASTR 20      // As [m][k] stride (conflict-free fragment loads)
#define SBSTR_NT 20   // Bs [n][k] stride
#define SBSTR_NN 136  // Bs [k][n] stride (136 mod 32 == 8 -> conflict-free)
#define SB_ELEMS 2560 // max(128*20, 16*136)

__device__ __forceinline__ uint32_t f2tf(float f) {
    uint32_t u;
    asm("cvt.rna.tf32.f32 %0, %1;" : "=r"(u) : "f"(f));
    return u;
}

__device__ __forceinline__ void mma8(float* c, const uint32_t* a, const uint32_t* b) {
    asm volatile(
        "mma.sync.aligned.m16n8k8.row.col.f32.tf32.tf32.f32 "
        "{%0,%1,%2,%3}, {%4,%5,%6,%7}, {%8,%9}, {%0,%1,%2,%3};\n"
        : "+f"(c[0]), "+f"(c[1]), "+f"(c[2]), "+f"(c[3])
        : "r"(a[0]), "r"(a[1]), "r"(a[2]), "r"(a[3]), "r"(b[0]), "r"(b[1]));
}

// C[m0:m0+128, n0:n0+128] = A[m0:,:K] * op(B)
// BL==0: B is [N,K] row-major (C = A * B^T).  BL==1: B is [K,N] row-major (C = A * B).
// All dims are multiples of the tile sizes for every call in this problem.
template <int BL>
__device__ __forceinline__ void gemm_core(
    const float* __restrict__ A, const float* __restrict__ B, float* __restrict__ C,
    int m0, int n0, int K, int lda, int ldb, int ldc)
{
    __shared__ uint32_t sa[2][BM * SASTR];
    __shared__ uint32_t sb[2][SB_ELEMS];

    const int tid = threadIdx.x;
    const int am = tid >> 2;            // 0..63 (rows am, am+64)
    const int ak = (tid & 3) << 2;      // 0,4,8,12
    const int bkr = tid >> 5;           // NN: 0..7 (rows bkr, bkr+8)
    const int bnc = (tid & 31) << 2;    // NN: 0..124

    const int warp = tid >> 5;
    const int lane = tid & 31;
    const int wm = (warp & 3) << 5;     // warp M offset: 0,32,64,96
    const int wn = (warp >> 2) << 6;    // warp N offset: 0,64
    const int g  = lane >> 2;           // groupID
    const int tg = lane & 3;            // thread-in-group

    float acc[2][8][4];
#pragma unroll
    for (int i = 0; i < 2; i++)
#pragma unroll
        for (int j = 0; j < 8; j++)
#pragma unroll
            for (int l = 0; l < 4; l++) acc[i][j][l] = 0.f;

    const int nk = K / BK;
    float4 ra0, ra1, rb0, rb1;

#define LOAD_TILE(kt) do {                                                        \
        const float* pa_ = A + (size_t)(m0 + am) * lda + (kt) * BK + ak;          \
        ra0 = *(const float4*)pa_;                                                \
        ra1 = *(const float4*)(pa_ + (size_t)64 * lda);                           \
        if (BL == 0) {                                                            \
            const float* pb_ = B + (size_t)(n0 + am) * ldb + (kt) * BK + ak;      \
            rb0 = *(const float4*)pb_;                                            \
            rb1 = *(const float4*)(pb_ + (size_t)64 * ldb);                       \
        } else {                                                                  \
            const float* pb_ = B + (size_t)((kt) * BK + bkr) * ldb + n0 + bnc;    \
            rb0 = *(const float4*)pb_;                                            \
            rb1 = *(const float4*)(pb_ + (size_t)8 * ldb);                        \
        }                                                                         \
    } while (0)

#define STORE_TILE(p) do {                                                        \
        uint32_t* da_ = &sa[p][am * SASTR + ak];                                  \
        da_[0] = f2tf(ra0.x); da_[1] = f2tf(ra0.y);                               \
        da_[2] = f2tf(ra0.z); da_[3] = f2tf(ra0.w);                               \
        uint32_t* da2_ = &sa[p][(am + 64) * SASTR + ak];                          \
        da2_[0] = f2tf(ra1.x); da2_[1] = f2tf(ra1.y);                             \
        da2_[2] = f2tf(ra1.z); da2_[3] = f2tf(ra1.w);                             \
        if (BL == 0) {                                                            \
            uint32_t* db_ = &sb[p][am * SBSTR_NT + ak];                           \
            db_[0] = f2tf(rb0.x); db_[1] = f2tf(rb0.y);                           \
            db_[2] = f2tf(rb0.z); db_[3] = f2tf(rb0.w);                           \
            uint32_t* db2_ = &sb[p][(am + 64) * SBSTR_NT + ak];                   \
            db2_[0] = f2tf(rb1.x); db2_[1] = f2tf(rb1.y);                         \
            db2_[2] = f2tf(rb1.z); db2_[3] = f2tf(rb1.w);                         \
        } else {                                                                  \
            uint32_t* db_ = &sb[p][bkr * SBSTR_NN + bnc];                         \
            db_[0] = f2tf(rb0.x); db_[1] = f2tf(rb0.y);                           \
            db_[2] = f2tf(rb0.z); db_[3] = f2tf(rb0.w);                           \
            uint32_t* db2_ = &sb[p][(bkr + 8) * SBSTR_NN + bnc];                  \
            db2_[0] = f2tf(rb1.x); db2_[1] = f2tf(rb1.y);                         \
            db2_[2] = f2tf(rb1.z); db2_[3] = f2tf(rb1.w);                         \
        }                                                                         \
    } while (0)

    LOAD_TILE(0);
    STORE_TILE(0);
    __syncthreads();

    for (int kt = 0; kt < nk; ++kt) {
        const int cur = kt & 1;
        if (kt + 1 < nk) LOAD_TILE(kt + 1);

#pragma unroll
        for (int ks = 0; ks < 2; ks++) {
            const int kb = ks * 8;
            uint32_t af[2][4];
#pragma unroll
            for (int mt = 0; mt < 2; mt++) {
                const int r = wm + mt * 16 + g;
                const uint32_t* base = &sa[cur][r * SASTR + kb + tg];
                af[mt][0] = base[0];
                af[mt][1] = base[8 * SASTR];
                af[mt][2] = base[4];
                af[mt][3] = base[8 * SASTR + 4];
            }
            uint32_t bf[8][2];
#pragma unroll
            for (int nt = 0; nt < 8; nt++) {
                const int c = wn + nt * 8 + g;
                if (BL == 0) {
                    const uint32_t* base = &sb[cur][c * SBSTR_NT + kb + tg];
                    bf[nt][0] = base[0];
                    bf[nt][1] = base[4];
                } else {
                    const uint32_t* base = &sb[cur][(kb + tg) * SBSTR_NN + c];
                    bf[nt][0] = base[0];
                    bf[nt][1] = base[4 * SBSTR_NN];
                }
            }
#pragma unroll
            for (int mt = 0; mt < 2; mt++)
#pragma unroll
                for (int nt = 0; nt < 8; nt++)
                    mma8(acc[mt][nt], af[mt], bf[nt]);
        }

        if (kt + 1 < nk) STORE_TILE(cur ^ 1);
        __syncthreads();
    }

#pragma unroll
    for (int mt = 0; mt < 2; mt++) {
        const int r = m0 + wm + mt * 16 + g;
#pragma unroll
        for (int nt = 0; nt < 8; nt++) {
            const int c = n0 + wn + nt * 8 + (tg << 1);
            float* p0 = C + (size_t)r * ldc + c;
            *(float2*)p0 = make_float2(acc[mt][nt][0], acc[mt][nt][1]);
            float* p1 = p0 + (size_t)8 * ldc;
            *(float2*)p1 = make_float2(acc[mt][nt][2], acc[mt][nt][3]);
        }
    }
#undef LOAD_TILE
#undef STORE_TILE
}

// ---------------- kernels ---------------------------------------------------

__global__ void __launch_bounds__(256) proj_q_kernel(const float* __restrict__ hs, const float* __restrict__ W) {
    gemm_core<0>(hs, W, g_q, blockIdx.y * BM, blockIdx.x * BN, HDIM, HDIM, HDIM, QLD);
}
__global__ void __launch_bounds__(256) proj_k_kernel(const float* __restrict__ hs, const float* __restrict__ W) {
    gemm_core<0>(hs, W, g_k, blockIdx.y * BM, blockIdx.x * BN, HDIM, HDIM, HDIM, KLD);
}
__global__ void __launch_bounds__(256) proj_v_kernel(const float* __restrict__ hs, const float* __restrict__ W) {
    gemm_core<0>(hs, W, g_v, blockIdx.y * BM, blockIdx.x * BN, HDIM, HDIM, HDIM, KLD);
}
__global__ void __launch_bounds__(256) out_proj_kernel(const float* __restrict__ W, float* __restrict__ out) {
    gemm_core<0>(g_attn, W, out, blockIdx.y * BM, blockIdx.x * BN, QLD, QLD, HDIM, HDIM);
}

// scores[z][i][j] = sum_d q[b,h,i,d] * k[b,kv,j,d]  (skip fully-masked blocks)
__global__ void __launch_bounds__(256) scores_kernel() {
    if (blockIdx.x > blockIdx.y) return;
    const int z = blockIdx.z, b = z >> 5, h = z & 31, kv = h >> 2;
    gemm_core<0>(g_q + (size_t)b * SEQ * QLD + h * HD,
                 g_k + (size_t)b * SEQ * KLD + kv * HD,
                 g_scores + (size_t)z * SEQ * SEQ,
                 blockIdx.y * BM, blockIdx.x * BN, HD, QLD, KLD, SEQ);
}

// attn[b,i,h*HD+d] = sum_j probs[z][i][j] * v[b,kv,j,d]; K bounded causally
__global__ void __launch_bounds__(256) pv_kernel() {
    const int z = blockIdx.z, b = z >> 5, h = z & 31, kv = h >> 2;
    const int m0 = blockIdx.y * BM;
    gemm_core<1>(g_scores + (size_t)z * SEQ * SEQ,
                 g_v + (size_t)b * SEQ * KLD + kv * HD,
                 g_attn + (size_t)b * SEQ * QLD + h * HD,
                 m0, 0, m0 + BM, SEQ, KLD, QLD);
}

// in-place RoPE on g_q
__global__ void rope_q(const float* __restrict__ cosT, const float* __restrict__ sinT) {
    const int row = blockIdx.x;
    const int s = row & (SEQ - 1);
    const float* cr = cosT + (size_t)s * HD;
    const float* sr = sinT + (size_t)s * HD;
    float* base = g_q + (size_t)row * QLD;
    for (int idx = threadIdx.x; idx < NH * 64; idx += blockDim.x) {
        const int hh = idx >> 6, d = idx & 63;
        float* p = base + hh * HD;
        const float x1 = p[d], x2 = p[d + 64];
        p[d]      = x1 * cr[d]      - x2 * sr[d];
        p[d + 64] = x2 * cr[d + 64] + x1 * sr[d + 64];
    }
}
// in-place RoPE on g_k
__global__ void rope_k(const float* __restrict__ cosT, const float* __restrict__ sinT) {
    const int row = blockIdx.x;
    const int s = row & (SEQ - 1);
    const float* cr = cosT + (size_t)s * HD;
    const float* sr = sinT + (size_t)s * HD;
    float* base = g_k + (size_t)row * KLD;
    for (int idx = threadIdx.x; idx < NKV * 64; idx += blockDim.x) {
        const int hh = idx >> 6, d = idx & 63;
        float* p = base + hh * HD;
        const float x1 = p[d], x2 = p[d + 64];
        p[d]      = x1 * cr[d]      - x2 * sr[d];
        p[d + 64] = x2 * cr[d + 64] + x1 * sr[d + 64];
    }
}

// causal softmax over row i (valid j in [0, i]); zeros above the diagonal
__global__ void __launch_bounds__(256) softmax_kernel() {
    const int i = blockIdx.x, z = blockIdx.y, tid = threadIdx.x;
    float* row = g_scores + (size_t)z * SEQ * SEQ + (size_t)i * SEQ;
    const int n = i + 1;
    const float scale = 0.08838834764831845f;  // 1/sqrt(128)

    float v[8];
    float m = -3.4e38f;
#pragma unroll
    for (int t = 0; t < 8; t++) {
        const int j = tid + (t << 8);
        v[t] = (j < n) ? row[j] * scale : -3.4e38f;
        m = fmaxf(m, v[t]);
    }
    __shared__ float red[8];
#pragma unroll
    for (int o = 16; o; o >>= 1) m = fmaxf(m, __shfl_xor_sync(0xffffffffu, m, o));
    if ((tid & 31) == 0) red[tid >> 5] = m;
    __syncthreads();
#pragma unroll
    for (int w = 0; w < 8; w++) m = fmaxf(m, red[w]);
    __syncthreads();

    float sum = 0.f;
#pragma unroll
    for (int t = 0; t < 8; t++) {
        const int j = tid + (t << 8);
        const float e = (j < n) ? __expf(v[t] - m) : 0.f;
        v[t] = e;
        sum += e;
    }
#pragma unroll
    for (int o = 16; o; o >>= 1) sum += __shfl_xor_sync(0xffffffffu, sum, o);
    if ((tid & 31) == 0) red[tid >> 5] = sum;
    __syncthreads();
    sum = 0.f;
#pragma unroll
    for (int w = 0; w < 8; w++) sum += red[w];
    const float inv = 1.0f / sum;
#pragma unroll
    for (int t = 0; t < 8; t++) {
        const int j = tid + (t << 8);
        row[j] = (j < n) ? v[t] * inv : 0.f;
    }
}

// ---------------- launch -----------------------------------------------------
extern "C" void kernel_launch(void* const* d_in, const int* in_sizes, int n_in,
                              void* d_out, int out_size) {
    (void)in_sizes; (void)n_in; (void)out_size;
    const float* hs   = (const float*)d_in[0];
    const float* Wq   = (const float*)d_in[1];
    const float* Wk   = (const float*)d_in[2];
    const float* Wv   = (const float*)d_in[3];
    const float* Wo   = (const float*)d_in[4];
    const float* cosT = (const float*)d_in[5];
    const float* sinT = (const float*)d_in[6];
    float* out = (float*)d_out;

    proj_q_kernel<<<dim3(QLD / BN, ROWS / BM), 256>>>(hs, Wq);
    proj_k_kernel<<<dim3(KLD / BN, ROWS / BM), 256>>>(hs, Wk);
    proj_v_kernel<<<dim3(KLD / BN, ROWS / BM), 256>>>(hs, Wv);
    rope_q<<<ROWS, 256>>>(cosT, sinT);
    rope_k<<<ROWS, 256>>>(cosT, sinT);
    scores_kernel<<<dim3(SEQ / BN, SEQ / BM, NBH), 256>>>();
    softmax_kernel<<<dim3(SEQ, NBH), 256>>>();
    pv_kernel<<<dim3(1, SEQ / BM, NBH), 256>>>();
    out_proj_kernel<<<dim3(HDIM / BN, ROWS / BM), 256>>>(Wo, out);
}

// round 3
// speedup vs baseline: 1.1941x; 1.1941x over previous
#include <cuda_runtime.h>
#include <cstdint>

#define SEQ 2048
#define NB 2
#define ROWS (NB * SEQ)      // 4096 total (b,s) rows
#define HDIM 4096
#define NH 32
#define NKV 8
#define HD 128
#define QLD (NH * HD)        // 4096
#define KLD (NKV * HD)       // 1024
#define NBH (NB * NH)        // 64

// ---------------- scratch (static device allocations; no cudaMalloc) -------
__device__ float g_q[(size_t)ROWS * QLD];                 // 64 MB
__device__ float g_k[(size_t)ROWS * KLD];                 // 16 MB
__device__ float g_v[(size_t)ROWS * KLD];                 // 16 MB
__device__ float g_attn[(size_t)ROWS * QLD];              // 64 MB
__device__ float g_scores[(size_t)NBH * SEQ * SEQ];       // 1 GiB
// tf32-pre-rounded copies of the inputs
__device__ float g_hs[(size_t)ROWS * HDIM];               // 64 MB
__device__ float g_wq[(size_t)QLD * HDIM];                // 64 MB
__device__ float g_wk[(size_t)KLD * HDIM];                // 16 MB
__device__ float g_wv[(size_t)KLD * HDIM];                // 16 MB
__device__ float g_wo[(size_t)HDIM * QLD];                // 64 MB

// ---------------- helpers ---------------------------------------------------
__device__ __forceinline__ uint32_t smem_u32(const void* p) {
    uint32_t a;
    asm("{ .reg .u64 t; cvta.to.shared.u64 t, %1; cvt.u32.u64 %0, t; }" : "=r"(a) : "l"(p));
    return a;
}
__device__ __forceinline__ uint32_t f2tf(float f) {
    uint32_t u;
    asm("cvt.rna.tf32.f32 %0, %1;" : "=r"(u) : "f"(f));
    return u;
}
__device__ __forceinline__ float round_tf(float f) {
    return __uint_as_float(f2tf(f));
}

#define CP_ASYNC16(dst, src) \
    asm volatile("cp.async.cg.shared.global [%0], [%1], 16;" :: "r"(dst), "l"(src) : "memory")
#define CP_COMMIT() asm volatile("cp.async.commit_group;" ::: "memory")
#define CP_WAIT(n)  asm volatile("cp.async.wait_group %0;" :: "n"(n) : "memory")

__device__ __forceinline__ void mma8(float* c, const uint32_t* a, const uint32_t* b) {
    asm volatile(
        "mma.sync.aligned.m16n8k8.row.col.f32.tf32.tf32.f32 "
        "{%0,%1,%2,%3}, {%4,%5,%6,%7}, {%8,%9}, {%0,%1,%2,%3};\n"
        : "+f"(c[0]), "+f"(c[1]), "+f"(c[2]), "+f"(c[3])
        : "r"(a[0]), "r"(a[1]), "r"(a[2]), "r"(a[3]), "r"(b[0]), "r"(b[1]));
}

// ============================================================================
// cp.async-pipelined tf32 GEMM core.
// Operands MUST be pre-rounded to tf32 (low 13 mantissa bits zero).
// BL==0: B is [N,K] row-major (C = A * B^T).  BL==1: B is [K,N] (C = A * B).
// RND: round C to tf32 on store.
// Tile 128x128, BK=16, 4-stage cp.async pipeline, 256 threads.
// ============================================================================
#define BK 16
#define NSTAGE 4
#define SASTR 20            // A smem row stride (floats)
#define SBSTR_NT 20
#define SBSTR_NN 136
#define SA_BYTES (128 * SASTR * 4)          // 10240
#define SB_BYTES (128 * SBSTR_NT * 4)       // 10240 (>= 16*136*4 = 8704)
#define STAGE_BYTES (SA_BYTES + SB_BYTES)   // 20480
#define GSMEM (NSTAGE * STAGE_BYTES)        // 81920

template <int BL, bool RND>
__device__ __forceinline__ void gemm_core(
    const float* __restrict__ A, const float* __restrict__ B, float* __restrict__ C,
    int m0, int n0, int K, int lda, int ldb, int ldc)
{
    extern __shared__ float dsm[];
    const uint32_t sbase = smem_u32(dsm);

    const int tid = threadIdx.x;
    const int am = tid >> 2;            // 0..63 (rows am, am+64)
    const int ak = (tid & 3) << 2;      // 0,4,8,12
    const int bkr = tid >> 5;           // NN: 0..7 (rows bkr, bkr+8)
    const int bnc = (tid & 31) << 2;    // NN: 0..124

    const int warp = tid >> 5;
    const int lane = tid & 31;
    const int wm = (warp & 3) << 5;     // 0,32,64,96
    const int wn = (warp >> 2) << 6;    // 0,64
    const int g  = lane >> 2;
    const int tg = lane & 3;

    float acc[2][8][4];
#pragma unroll
    for (int i = 0; i < 2; i++)
#pragma unroll
        for (int j = 0; j < 8; j++)
#pragma unroll
            for (int l = 0; l < 4; l++) acc[i][j][l] = 0.f;

    const int nk = K / BK;

#define LOAD_STAGE(s) do {                                                         \
        const uint32_t sa_u = sbase + ((s) & (NSTAGE - 1)) * STAGE_BYTES;          \
        const uint32_t sb_u = sa_u + SA_BYTES;                                     \
        const float* pa_ = A + (size_t)(m0 + am) * lda + (s) * BK + ak;            \
        CP_ASYNC16(sa_u + (uint32_t)(am * SASTR + ak) * 4u, pa_);                  \
        CP_ASYNC16(sa_u + (uint32_t)((am + 64) * SASTR + ak) * 4u,                 \
                   pa_ + (size_t)64 * lda);                                        \
        if (BL == 0) {                                                             \
            const float* pb_ = B + (size_t)(n0 + am) * ldb + (s) * BK + ak;        \
            CP_ASYNC16(sb_u + (uint32_t)(am * SBSTR_NT + ak) * 4u, pb_);           \
            CP_ASYNC16(sb_u + (uint32_t)((am + 64) * SBSTR_NT + ak) * 4u,          \
                       pb_ + (size_t)64 * ldb);                                    \
        } else {                                                                   \
            const float* pb_ = B + (size_t)((s) * BK + bkr) * ldb + n0 + bnc;      \
            CP_ASYNC16(sb_u + (uint32_t)(bkr * SBSTR_NN + bnc) * 4u, pb_);         \
            CP_ASYNC16(sb_u + (uint32_t)((bkr + 8) * SBSTR_NN + bnc) * 4u,         \
                       pb_ + (size_t)8 * ldb);                                     \
        }                                                                          \
    } while (0)

    // prologue: stages 0..NSTAGE-2
#pragma unroll
    for (int s = 0; s < NSTAGE - 1; s++) {
        if (s < nk) LOAD_STAGE(s);
        CP_COMMIT();
    }

    for (int kt = 0; kt < nk; kt++) {
        CP_WAIT(NSTAGE - 2);
        __syncthreads();
        if (kt + NSTAGE - 1 < nk) LOAD_STAGE(kt + NSTAGE - 1);
        CP_COMMIT();

        const uint32_t* sa = (const uint32_t*)dsm + (size_t)(kt & (NSTAGE - 1)) * (STAGE_BYTES / 4);
        const uint32_t* sb = sa + SA_BYTES / 4;

#pragma unroll
        for (int ks = 0; ks < 2; ks++) {
            const int kb = ks * 8;
            uint32_t af[2][4];
#pragma unroll
            for (int mt = 0; mt < 2; mt++) {
                const int r = wm + mt * 16 + g;
                const uint32_t* base = &sa[r * SASTR + kb + tg];
                af[mt][0] = base[0];
                af[mt][1] = base[8 * SASTR];
                af[mt][2] = base[4];
                af[mt][3] = base[8 * SASTR + 4];
            }
            uint32_t bf[8][2];
#pragma unroll
            for (int nt = 0; nt < 8; nt++) {
                const int c = wn + nt * 8 + g;
                if (BL == 0) {
                    const uint32_t* base = &sb[c * SBSTR_NT + kb + tg];
                    bf[nt][0] = base[0];
                    bf[nt][1] = base[4];
                } else {
                    const uint32_t* base = &sb[(kb + tg) * SBSTR_NN + c];
                    bf[nt][0] = base[0];
                    bf[nt][1] = base[4 * SBSTR_NN];
                }
            }
#pragma unroll
            for (int mt = 0; mt < 2; mt++)
#pragma unroll
                for (int nt = 0; nt < 8; nt++)
                    mma8(acc[mt][nt], af[mt], bf[nt]);
        }
        __syncthreads();
    }

#pragma unroll
    for (int mt = 0; mt < 2; mt++) {
        const int r = m0 + wm + mt * 16 + g;
#pragma unroll
        for (int nt = 0; nt < 8; nt++) {
            const int c = n0 + wn + nt * 8 + (tg << 1);
            float v0 = acc[mt][nt][0], v1 = acc[mt][nt][1];
            float v2 = acc[mt][nt][2], v3 = acc[mt][nt][3];
            if (RND) {
                v0 = round_tf(v0); v1 = round_tf(v1);
                v2 = round_tf(v2); v3 = round_tf(v3);
            }
            float* p0 = C + (size_t)r * ldc + c;
            *(float2*)p0 = make_float2(v0, v1);
            float* p1 = p0 + (size_t)8 * ldc;
            *(float2*)p1 = make_float2(v2, v3);
        }
    }
#undef LOAD_STAGE
}

// ---------------- GEMM wrappers ---------------------------------------------
__global__ void __launch_bounds__(256, 2) k_proj_q() {
    gemm_core<0, false>(g_hs, g_wq, g_q, blockIdx.y * 128, blockIdx.x * 128,
                        HDIM, HDIM, HDIM, QLD);
}
__global__ void __launch_bounds__(256, 2) k_proj_k() {
    gemm_core<0, false>(g_hs, g_wk, g_k, blockIdx.y * 128, blockIdx.x * 128,
                        HDIM, HDIM, HDIM, KLD);
}
__global__ void __launch_bounds__(256, 2) k_proj_v() {
    gemm_core<0, true>(g_hs, g_wv, g_v, blockIdx.y * 128, blockIdx.x * 128,
                       HDIM, HDIM, HDIM, KLD);
}
__global__ void __launch_bounds__(256, 2) k_out_proj(float* __restrict__ out) {
    gemm_core<0, false>(g_attn, g_wo, out, blockIdx.y * 128, blockIdx.x * 128,
                        QLD, QLD, HDIM, HDIM);
}
// scores[z][i][j] = sum_d q[...]k[...]; skip fully-masked causal blocks
__global__ void __launch_bounds__(256, 2) k_scores() {
    if (blockIdx.x > blockIdx.y) return;
    const int z = blockIdx.z, b = z >> 5, h = z & 31, kv = h >> 2;
    gemm_core<0, false>(g_q + (size_t)b * SEQ * QLD + h * HD,
                        g_k + (size_t)b * SEQ * KLD + kv * HD,
                        g_scores + (size_t)z * SEQ * SEQ,
                        blockIdx.y * 128, blockIdx.x * 128, HD, QLD, KLD, SEQ);
}
// attn = probs @ V, K bounded causally; output rounded (feeds out_proj)
__global__ void __launch_bounds__(256, 2) k_pv() {
    const int z = blockIdx.z, b = z >> 5, h = z & 31, kv = h >> 2;
    const int m0 = blockIdx.y * 128;
    gemm_core<1, true>(g_scores + (size_t)z * SEQ * SEQ,
                       g_v + (size_t)b * SEQ * KLD + kv * HD,
                       g_attn + (size_t)b * SEQ * QLD + h * HD,
                       m0, 0, m0 + 128, SEQ, KLD, QLD);
}

// ---------------- tf32 rounding prepass --------------------------------------
__global__ void round_copy(float* __restrict__ dst, const float* __restrict__ src, int n4) {
    const int stride = gridDim.x * blockDim.x;
    for (int i = blockIdx.x * blockDim.x + threadIdx.x; i < n4; i += stride) {
        float4 v = ((const float4*)src)[i];
        v.x = round_tf(v.x); v.y = round_tf(v.y);
        v.z = round_tf(v.z); v.w = round_tf(v.w);
        ((float4*)dst)[i] = v;
    }
}

// ---------------- RoPE (writes tf32-rounded) ---------------------------------
__global__ void rope_q(const float* __restrict__ cosT, const float* __restrict__ sinT) {
    const int row = blockIdx.x;
    const int s = row & (SEQ - 1);
    const float* cr = cosT + (size_t)s * HD;
    const float* sr = sinT + (size_t)s * HD;
    float* base = g_q + (size_t)row * QLD;
    for (int idx = threadIdx.x; idx < NH * 64; idx += blockDim.x) {
        const int hh = idx >> 6, d = idx & 63;
        float* p = base + hh * HD;
        const float x1 = p[d], x2 = p[d + 64];
        p[d]      = round_tf(x1 * cr[d]      - x2 * sr[d]);
        p[d + 64] = round_tf(x2 * cr[d + 64] + x1 * sr[d + 64]);
    }
}
__global__ void rope_k(const float* __restrict__ cosT, const float* __restrict__ sinT) {
    const int row = blockIdx.x;
    const int s = row & (SEQ - 1);
    const float* cr = cosT + (size_t)s * HD;
    const float* sr = sinT + (size_t)s * HD;
    float* base = g_k + (size_t)row * KLD;
    for (int idx = threadIdx.x; idx < NKV * 64; idx += blockDim.x) {
        const int hh = idx >> 6, d = idx & 63;
        float* p = base + hh * HD;
        const float x1 = p[d], x2 = p[d + 64];
        p[d]      = round_tf(x1 * cr[d]      - x2 * sr[d]);
        p[d + 64] = round_tf(x2 * cr[d + 64] + x1 * sr[d + 64]);
    }
}

// ---------------- causal softmax (writes tf32-rounded probs) ------------------
__global__ void __launch_bounds__(256) softmax_kernel() {
    const int i = blockIdx.x, z = blockIdx.y, tid = threadIdx.x;
    float* row = g_scores + (size_t)z * SEQ * SEQ + (size_t)i * SEQ;
    const int n = i + 1;
    const float scale = 0.08838834764831845f;  // 1/sqrt(128)

    float v[8];
    float m = -3.4e38f;
#pragma unroll
    for (int t = 0; t < 8; t++) {
        const int j = tid + (t << 8);
        v[t] = (j < n) ? row[j] * scale : -3.4e38f;
        m = fmaxf(m, v[t]);
    }
    __shared__ float red[8];
#pragma unroll
    for (int o = 16; o; o >>= 1) m = fmaxf(m, __shfl_xor_sync(0xffffffffu, m, o));
    if ((tid & 31) == 0) red[tid >> 5] = m;
    __syncthreads();
#pragma unroll
    for (int w = 0; w < 8; w++) m = fmaxf(m, red[w]);
    __syncthreads();

    float sum = 0.f;
#pragma unroll
    for (int t = 0; t < 8; t++) {
        const int j = tid + (t << 8);
        const float e = (j < n) ? __expf(v[t] - m) : 0.f;
        v[t] = e;
        sum += e;
    }
#pragma unroll
    for (int o = 16; o; o >>= 1) sum += __shfl_xor_sync(0xffffffffu, sum, o);
    if ((tid & 31) == 0) red[tid >> 5] = sum;
    __syncthreads();
    sum = 0.f;
#pragma unroll
    for (int w = 0; w < 8; w++) sum += red[w];
    const float inv = 1.0f / sum;
#pragma unroll
    for (int t = 0; t < 8; t++) {
        const int j = tid + (t << 8);
        row[j] = (j < n) ? round_tf(v[t] * inv) : 0.f;
    }
}

// ---------------- launch -----------------------------------------------------
extern "C" void kernel_launch(void* const* d_in, const int* in_sizes, int n_in,
                              void* d_out, int out_size) {
    (void)in_sizes; (void)n_in; (void)out_size;
    const float* hs   = (const float*)d_in[0];
    const float* Wq   = (const float*)d_in[1];
    const float* Wk   = (const float*)d_in[2];
    const float* Wv   = (const float*)d_in[3];
    const float* Wo   = (const float*)d_in[4];
    const float* cosT = (const float*)d_in[5];
    const float* sinT = (const float*)d_in[6];
    float* out = (float*)d_out;

    static bool attr_set = false;
    if (!attr_set) {
        cudaFuncSetAttribute(k_proj_q,    cudaFuncAttributeMaxDynamicSharedMemorySize, GSMEM);
        cudaFuncSetAttribute(k_proj_k,    cudaFuncAttributeMaxDynamicSharedMemorySize, GSMEM);
        cudaFuncSetAttribute(k_proj_v,    cudaFuncAttributeMaxDynamicSharedMemorySize, GSMEM);
        cudaFuncSetAttribute(k_out_proj,  cudaFuncAttributeMaxDynamicSharedMemorySize, GSMEM);
        cudaFuncSetAttribute(k_scores,    cudaFuncAttributeMaxDynamicSharedMemorySize, GSMEM);
        cudaFuncSetAttribute(k_pv,        cudaFuncAttributeMaxDynamicSharedMemorySize, GSMEM);
        attr_set = true;
    }

    float* phs;  cudaGetSymbolAddress((void**)&phs, g_hs);
    float* pwq;  cudaGetSymbolAddress((void**)&pwq, g_wq);
    float* pwk;  cudaGetSymbolAddress((void**)&pwk, g_wk);
    float* pwv;  cudaGetSymbolAddress((void**)&pwv, g_wv);
    float* pwo;  cudaGetSymbolAddress((void**)&pwo, g_wo);

    round_copy<<<1184, 256>>>(phs, hs, (int)((size_t)ROWS * HDIM / 4));
    round_copy<<<1184, 256>>>(pwq, Wq, (int)((size_t)QLD * HDIM / 4));
    round_copy<<<1184, 256>>>(pwk, Wk, (int)((size_t)KLD * HDIM / 4));
    round_copy<<<1184, 256>>>(pwv, Wv, (int)((size_t)KLD * HDIM / 4));
    round_copy<<<1184, 256>>>(pwo, Wo, (int)((size_t)HDIM * QLD / 4));

    k_proj_q<<<dim3(QLD / 128, ROWS / 128), 256, GSMEM>>>();
    k_proj_k<<<dim3(KLD / 128, ROWS / 128), 256, GSMEM>>>();
    k_proj_v<<<dim3(KLD / 128, ROWS / 128), 256, GSMEM>>>();
    rope_q<<<ROWS, 256>>>(cosT, sinT);
    rope_k<<<ROWS, 256>>>(cosT, sinT);
    k_scores<<<dim3(SEQ / 128, SEQ / 128, NBH), 256, GSMEM>>>();
    softmax_kernel<<<dim3(SEQ, NBH), 256>>>();
    k_pv<<<dim3(1, SEQ / 128, NBH), 256, GSMEM>>>();
    k_out_proj<<<dim3(HDIM / 128, ROWS / 128), 256, GSMEM>>>(out);
}

// round 4
// speedup vs baseline: 1.3475x; 1.1284x over previous
#include <cuda_runtime.h>
#include <cstdint>

#define SEQ 2048
#define NB 2
#define ROWS (NB * SEQ)      // 4096 total (b,s) rows
#define HDIM 4096
#define NH 32
#define NKV 8
#define HD 128
#define QLD (NH * HD)        // 4096
#define KLD (NKV * HD)       // 1024
#define NBH (NB * NH)        // 64

// ---------------- scratch (static device allocations; no cudaMalloc) -------
__device__ float g_q[(size_t)ROWS * QLD];                 // 64 MB
__device__ float g_k[(size_t)ROWS * KLD];                 // 16 MB
__device__ float g_v[(size_t)ROWS * KLD];                 // 16 MB
__device__ float g_attn[(size_t)ROWS * QLD];              // 64 MB
// tf32-pre-rounded copies of the inputs
__device__ float g_hs[(size_t)ROWS * HDIM];               // 64 MB
__device__ float g_wq[(size_t)QLD * HDIM];                // 64 MB
__device__ float g_wk[(size_t)KLD * HDIM];                // 16 MB
__device__ float g_wv[(size_t)KLD * HDIM];                // 16 MB
__device__ float g_wo[(size_t)HDIM * QLD];                // 64 MB

// ---------------- helpers ---------------------------------------------------
__device__ __forceinline__ uint32_t smem_u32(const void* p) {
    uint32_t a;
    asm("{ .reg .u64 t; cvta.to.shared.u64 t, %1; cvt.u32.u64 %0, t; }" : "=r"(a) : "l"(p));
    return a;
}
__device__ __forceinline__ uint32_t f2tf(float f) {
    uint32_t u;
    asm("cvt.rna.tf32.f32 %0, %1;" : "=r"(u) : "f"(f));
    return u;
}
__device__ __forceinline__ float round_tf(float f) {
    return __uint_as_float(f2tf(f));
}

#define CP_ASYNC16(dst, src) \
    asm volatile("cp.async.cg.shared.global [%0], [%1], 16;" :: "r"(dst), "l"(src) : "memory")
#define CP_COMMIT() asm volatile("cp.async.commit_group;" ::: "memory")
#define CP_WAIT(n)  asm volatile("cp.async.wait_group %0;" :: "n"(n) : "memory")

__device__ __forceinline__ void mma8(float* c, const uint32_t* a, const uint32_t* b) {
    asm volatile(
        "mma.sync.aligned.m16n8k8.row.col.f32.tf32.tf32.f32 "
        "{%0,%1,%2,%3}, {%4,%5,%6,%7}, {%8,%9}, {%0,%1,%2,%3};\n"
        : "+f"(c[0]), "+f"(c[1]), "+f"(c[2]), "+f"(c[3])
        : "r"(a[0]), "r"(a[1]), "r"(a[2]), "r"(a[3]), "r"(b[0]), "r"(b[1]));
}

// ============================================================================
// cp.async-pipelined tf32 GEMM core (projections).
// Operands MUST be pre-rounded to tf32.
// B is [N,K] row-major (C = A * B^T).
// Tile 128x128, BK=16, 4-stage cp.async pipeline, 256 threads.
// ============================================================================
#define BK 16
#define NSTAGE 4
#define SASTR 20
#define SBSTR_NT 20
#define SA_BYTES (128 * SASTR * 4)          // 10240
#define SB_BYTES (128 * SBSTR_NT * 4)       // 10240
#define STAGE_BYTES (SA_BYTES + SB_BYTES)   // 20480
#define GSMEM (NSTAGE * STAGE_BYTES)        // 81920

template <bool RND>
__device__ __forceinline__ void gemm_core(
    const float* __restrict__ A, const float* __restrict__ B, float* __restrict__ C,
    int m0, int n0, int K, int lda, int ldb, int ldc)
{
    extern __shared__ float dsm[];
    const uint32_t sbase = smem_u32(dsm);

    const int tid = threadIdx.x;
    const int am = tid >> 2;
    const int ak = (tid & 3) << 2;

    const int warp = tid >> 5;
    const int lane = tid & 31;
    const int wm = (warp & 3) << 5;
    const int wn = (warp >> 2) << 6;
    const int g  = lane >> 2;
    const int tg = lane & 3;

    float acc[2][8][4];
#pragma unroll
    for (int i = 0; i < 2; i++)
#pragma unroll
        for (int j = 0; j < 8; j++)
#pragma unroll
            for (int l = 0; l < 4; l++) acc[i][j][l] = 0.f;

    const int nk = K / BK;

#define LOAD_STAGE(s) do {                                                         \
        const uint32_t sa_u = sbase + ((s) & (NSTAGE - 1)) * STAGE_BYTES;          \
        const uint32_t sb_u = sa_u + SA_BYTES;                                     \
        const float* pa_ = A + (size_t)(m0 + am) * lda + (s) * BK + ak;            \
        CP_ASYNC16(sa_u + (uint32_t)(am * SASTR + ak) * 4u, pa_);                  \
        CP_ASYNC16(sa_u + (uint32_t)((am + 64) * SASTR + ak) * 4u,                 \
                   pa_ + (size_t)64 * lda);                                        \
        const float* pb_ = B + (size_t)(n0 + am) * ldb + (s) * BK + ak;            \
        CP_ASYNC16(sb_u + (uint32_t)(am * SBSTR_NT + ak) * 4u, pb_);               \
        CP_ASYNC16(sb_u + (uint32_t)((am + 64) * SBSTR_NT + ak) * 4u,              \
                   pb_ + (size_t)64 * ldb);                                        \
    } while (0)

#pragma unroll
    for (int s = 0; s < NSTAGE - 1; s++) {
        if (s < nk) LOAD_STAGE(s);
        CP_COMMIT();
    }

    for (int kt = 0; kt < nk; kt++) {
        CP_WAIT(NSTAGE - 2);
        __syncthreads();
        if (kt + NSTAGE - 1 < nk) LOAD_STAGE(kt + NSTAGE - 1);
        CP_COMMIT();

        const uint32_t* sa = (const uint32_t*)dsm + (size_t)(kt & (NSTAGE - 1)) * (STAGE_BYTES / 4);
        const uint32_t* sb = sa + SA_BYTES / 4;

#pragma unroll
        for (int ks = 0; ks < 2; ks++) {
            const int kb = ks * 8;
            uint32_t af[2][4];
#pragma unroll
            for (int mt = 0; mt < 2; mt++) {
                const int r = wm + mt * 16 + g;
                const uint32_t* base = &sa[r * SASTR + kb + tg];
                af[mt][0] = base[0];
                af[mt][1] = base[8 * SASTR];
                af[mt][2] = base[4];
                af[mt][3] = base[8 * SASTR + 4];
            }
            uint32_t bf[8][2];
#pragma unroll
            for (int nt = 0; nt < 8; nt++) {
                const int c = wn + nt * 8 + g;
                const uint32_t* base = &sb[c * SBSTR_NT + kb + tg];
                bf[nt][0] = base[0];
                bf[nt][1] = base[4];
            }
#pragma unroll
            for (int mt = 0; mt < 2; mt++)
#pragma unroll
                for (int nt = 0; nt < 8; nt++)
                    mma8(acc[mt][nt], af[mt], bf[nt]);
        }
        __syncthreads();
    }

#pragma unroll
    for (int mt = 0; mt < 2; mt++) {
        const int r = m0 + wm + mt * 16 + g;
#pragma unroll
        for (int nt = 0; nt < 8; nt++) {
            const int c = n0 + wn + nt * 8 + (tg << 1);
            float v0 = acc[mt][nt][0], v1 = acc[mt][nt][1];
            float v2 = acc[mt][nt][2], v3 = acc[mt][nt][3];
            if (RND) {
                v0 = round_tf(v0); v1 = round_tf(v1);
                v2 = round_tf(v2); v3 = round_tf(v3);
            }
            float* p0 = C + (size_t)r * ldc + c;
            *(float2*)p0 = make_float2(v0, v1);
            float* p1 = p0 + (size_t)8 * ldc;
            *(float2*)p1 = make_float2(v2, v3);
        }
    }
#undef LOAD_STAGE
}

// ---------------- projection wrappers ----------------------------------------
__global__ void __launch_bounds__(256, 2) k_proj_q() {
    gemm_core<false>(g_hs, g_wq, g_q, blockIdx.y * 128, blockIdx.x * 128,
                     HDIM, HDIM, HDIM, QLD);
}
__global__ void __launch_bounds__(256, 2) k_proj_k() {
    gemm_core<false>(g_hs, g_wk, g_k, blockIdx.y * 128, blockIdx.x * 128,
                     HDIM, HDIM, HDIM, KLD);
}
__global__ void __launch_bounds__(256, 2) k_proj_v() {
    gemm_core<true>(g_hs, g_wv, g_v, blockIdx.y * 128, blockIdx.x * 128,
                    HDIM, HDIM, HDIM, KLD);
}
__global__ void __launch_bounds__(256, 2) k_out_proj(float* __restrict__ out) {
    gemm_core<false>(g_attn, g_wo, out, blockIdx.y * 128, blockIdx.x * 128,
                     QLD, QLD, HDIM, HDIM);
}

// ============================================================================
// Fused flash attention (causal, online softmax).
// Grid (16 q-blocks [reversed], 64 z).  256 threads = 8 warps, 16 Q rows each.
// KV tiles of 64 rows, double-buffered cp.async.  All math in registers;
// Q fragments register-resident for the whole KV loop.
// ============================================================================
#define FKSTR 132   // K smem row stride (floats)
#define FVSTR 136   // V smem row stride
#define FK_U32 (64 * FKSTR)       // 8448
#define FV_U32 (64 * FVSTR)       // 8704
#define FSMEM ((2 * FK_U32 + 2 * FV_U32) * 4)   // 137216 bytes

__global__ void __launch_bounds__(256, 1) k_flash() {
    extern __shared__ uint32_t fsm[];
    const uint32_t sbase = smem_u32(fsm);

    const int tid = threadIdx.x;
    const int wid = tid >> 5, lane = tid & 31;
    const int g = lane >> 2, tg = lane & 3;
    const int wm = wid * 16;

    const int z = blockIdx.y, b = z >> 5, h = z & 31, kvh = h >> 2;
    const int qb = (int)(gridDim.x - 1 - blockIdx.x);   // heavy blocks first
    const int q0 = qb * 128;
    const int nkv = 2 * qb + 2;                          // KV tiles covering [0, q0+128)

    const float* Qp = g_q + (size_t)(b * SEQ + q0) * QLD + h * HD;
    const float* Kp = g_k + (size_t)b * SEQ * KLD + kvh * HD;
    const float* Vp = g_v + (size_t)b * SEQ * KLD + kvh * HD;

    // ---- stage Q tile (128x128) into smem [row*FKSTR + col], then load frags
#pragma unroll
    for (int i = 0; i < 16; i++) {
        const int op = tid + i * 256;
        const int row = op >> 5, c = (op & 31) << 2;
        CP_ASYNC16(sbase + (uint32_t)(row * FKSTR + c) * 4u, Qp + (size_t)row * QLD + c);
    }
    CP_COMMIT();
    CP_WAIT(0);
    __syncthreads();

    uint32_t qf[16][4];   // A fragments: rows wm+g / wm+g+8, cols ks*8+tg / +4
#pragma unroll
    for (int ks = 0; ks < 16; ks++) {
        const uint32_t* bp = fsm + (wm + g) * FKSTR + ks * 8 + tg;
        qf[ks][0] = bp[0];
        qf[ks][1] = bp[8 * FKSTR];
        qf[ks][2] = bp[4];
        qf[ks][3] = bp[8 * FKSTR + 4];
    }
    __syncthreads();

    const uint32_t* kbuf0 = fsm;
    const uint32_t* kbuf1 = fsm + FK_U32;
    const uint32_t* vbuf0 = fsm + 2 * FK_U32;
    const uint32_t* vbuf1 = vbuf0 + FV_U32;
    const uint32_t kbu[2] = { sbase, sbase + FK_U32 * 4u };
    const uint32_t vbu[2] = { sbase + 2u * FK_U32 * 4u, sbase + 2u * FK_U32 * 4u + FV_U32 * 4u };

#define LOAD_KV(t) do {                                                        \
        const int kv0_ = (t) * 64, p_ = (t) & 1;                               \
        _Pragma("unroll")                                                      \
        for (int i_ = 0; i_ < 8; i_++) {                                       \
            const int op_ = tid + i_ * 256;                                    \
            const int row_ = op_ >> 5, c_ = (op_ & 31) << 2;                   \
            CP_ASYNC16(kbu[p_] + (uint32_t)(row_ * FKSTR + c_) * 4u,           \
                       Kp + (size_t)(kv0_ + row_) * KLD + c_);                 \
            CP_ASYNC16(vbu[p_] + (uint32_t)(row_ * FVSTR + c_) * 4u,           \
                       Vp + (size_t)(kv0_ + row_) * KLD + c_);                 \
        }                                                                      \
        CP_COMMIT();                                                           \
    } while (0)

    LOAD_KV(0);
    LOAD_KV(1);   // nkv >= 2 always

    float mrow0 = -1e30f, mrow1 = -1e30f;
    float lrow0 = 0.f, lrow1 = 0.f;
    float o[16][4];
#pragma unroll
    for (int i = 0; i < 16; i++)
#pragma unroll
        for (int j = 0; j < 4; j++) o[i][j] = 0.f;

    const float sc = 0.08838834764831845f;   // 1/sqrt(128)
    const int r0g = q0 + wm + g, r1g = r0g + 8;
    const int l1 = (lane & ~3) | (tg >> 1);
    const bool odd = (tg & 1) != 0;

    for (int t = 0; t < nkv; t++) {
        const int p = t & 1, kv0 = t * 64;
        if (t + 1 < nkv) { CP_WAIT(1); } else { CP_WAIT(0); }
        __syncthreads();

        // ---- S = Q K^T  (16 Q rows x 64 KV cols per warp)
        float sacc[8][4];
#pragma unroll
        for (int nt = 0; nt < 8; nt++)
#pragma unroll
            for (int j = 0; j < 4; j++) sacc[nt][j] = 0.f;

        const uint32_t* kb = p ? kbuf1 : kbuf0;
#pragma unroll
        for (int ks = 0; ks < 16; ks++) {
#pragma unroll
            for (int nt = 0; nt < 8; nt++) {
                uint32_t bf[2];
                const uint32_t* bp = kb + (nt * 8 + g) * FKSTR + ks * 8 + tg;
                bf[0] = bp[0];
                bf[1] = bp[4];
                mma8(sacc[nt], qf[ks], bf);
            }
        }

        // ---- scale + causal mask + row max
        float mnew0 = mrow0, mnew1 = mrow1;
        const bool domask = (kv0 + 63 > q0);
#pragma unroll
        for (int nt = 0; nt < 8; nt++) {
            const int c0 = kv0 + nt * 8 + 2 * tg, c1 = c0 + 1;
            float v0 = sacc[nt][0] * sc, v1 = sacc[nt][1] * sc;
            float v2 = sacc[nt][2] * sc, v3 = sacc[nt][3] * sc;
            if (domask) {
                if (c0 > r0g) v0 = -1e30f;
                if (c1 > r0g) v1 = -1e30f;
                if (c0 > r1g) v2 = -1e30f;
                if (c1 > r1g) v3 = -1e30f;
            }
            sacc[nt][0] = v0; sacc[nt][1] = v1; sacc[nt][2] = v2; sacc[nt][3] = v3;
            mnew0 = fmaxf(mnew0, fmaxf(v0, v1));
            mnew1 = fmaxf(mnew1, fmaxf(v2, v3));
        }
        mnew0 = fmaxf(mnew0, __shfl_xor_sync(0xffffffffu, mnew0, 1));
        mnew0 = fmaxf(mnew0, __shfl_xor_sync(0xffffffffu, mnew0, 2));
        mnew1 = fmaxf(mnew1, __shfl_xor_sync(0xffffffffu, mnew1, 1));
        mnew1 = fmaxf(mnew1, __shfl_xor_sync(0xffffffffu, mnew1, 2));

        const float f0 = __expf(mrow0 - mnew0);
        const float f1 = __expf(mrow1 - mnew1);

        float rs0 = 0.f, rs1 = 0.f;
#pragma unroll
        for (int nt = 0; nt < 8; nt++) {
            const float e0 = __expf(sacc[nt][0] - mnew0);
            const float e1 = __expf(sacc[nt][1] - mnew0);
            const float e2 = __expf(sacc[nt][2] - mnew1);
            const float e3 = __expf(sacc[nt][3] - mnew1);
            sacc[nt][0] = e0; sacc[nt][1] = e1; sacc[nt][2] = e2; sacc[nt][3] = e3;
            rs0 += e0 + e1;
            rs1 += e2 + e3;
        }
        rs0 += __shfl_xor_sync(0xffffffffu, rs0, 1);
        rs0 += __shfl_xor_sync(0xffffffffu, rs0, 2);
        rs1 += __shfl_xor_sync(0xffffffffu, rs1, 1);
        rs1 += __shfl_xor_sync(0xffffffffu, rs1, 2);

        lrow0 = lrow0 * f0 + rs0;
        lrow1 = lrow1 * f1 + rs1;
        mrow0 = mnew0;
        mrow1 = mnew1;

#pragma unroll
        for (int nt2 = 0; nt2 < 16; nt2++) {
            o[nt2][0] *= f0; o[nt2][1] *= f0;
            o[nt2][2] *= f1; o[nt2][3] *= f1;
        }

        // ---- O += P V  (P fragments via intra-quad shuffles from S accum)
        const uint32_t* vb_ = p ? vbuf1 : vbuf0;
#pragma unroll
        for (int ks2 = 0; ks2 < 8; ks2++) {
            const float c0 = sacc[ks2][0], c1 = sacc[ks2][1];
            const float c2 = sacc[ks2][2], c3 = sacc[ks2][3];
            const float v00 = __shfl_sync(0xffffffffu, c0, l1);
            const float v01 = __shfl_sync(0xffffffffu, c1, l1);
            const float v10 = __shfl_sync(0xffffffffu, c2, l1);
            const float v11 = __shfl_sync(0xffffffffu, c3, l1);
            const float w00 = __shfl_sync(0xffffffffu, c0, l1 + 2);
            const float w01 = __shfl_sync(0xffffffffu, c1, l1 + 2);
            const float w10 = __shfl_sync(0xffffffffu, c2, l1 + 2);
            const float w11 = __shfl_sync(0xffffffffu, c3, l1 + 2);
            uint32_t pa[4];
            pa[0] = f2tf(odd ? v01 : v00);   // (row g,   col ks2*8+tg)
            pa[1] = f2tf(odd ? v11 : v10);   // (row g+8, col ks2*8+tg)
            pa[2] = f2tf(odd ? w01 : w00);   // (row g,   col ks2*8+tg+4)
            pa[3] = f2tf(odd ? w11 : w10);   // (row g+8, col ks2*8+tg+4)
#pragma unroll
            for (int nt2 = 0; nt2 < 16; nt2++) {
                uint32_t bf[2];
                const uint32_t* bp = vb_ + (ks2 * 8 + tg) * FVSTR + nt2 * 8 + g;
                bf[0] = bp[0];
                bf[1] = bp[4 * FVSTR];
                mma8(o[nt2], pa, bf);
            }
        }

        __syncthreads();   // all warps done with buffer p before refill
        if (t + 2 < nkv) LOAD_KV(t + 2);
    }

    // ---- epilogue: normalize, tf32-round (feeds out_proj), store
    const float inv0 = 1.f / lrow0;
    const float inv1 = 1.f / lrow1;
    float* orow0 = g_attn + (size_t)(b * SEQ + r0g) * QLD + h * HD;
    float* orow1 = g_attn + (size_t)(b * SEQ + r1g) * QLD + h * HD;
#pragma unroll
    for (int nt2 = 0; nt2 < 16; nt2++) {
        const int c = nt2 * 8 + 2 * tg;
        *(float2*)(orow0 + c) = make_float2(round_tf(o[nt2][0] * inv0),
                                            round_tf(o[nt2][1] * inv0));
        *(float2*)(orow1 + c) = make_float2(round_tf(o[nt2][2] * inv1),
                                            round_tf(o[nt2][3] * inv1));
    }
#undef LOAD_KV
}

// ---------------- tf32 rounding prepass --------------------------------------
__global__ void round_copy(float* __restrict__ dst, const float* __restrict__ src, int n4) {
    const int stride = gridDim.x * blockDim.x;
    for (int i = blockIdx.x * blockDim.x + threadIdx.x; i < n4; i += stride) {
        float4 v = ((const float4*)src)[i];
        v.x = round_tf(v.x); v.y = round_tf(v.y);
        v.z = round_tf(v.z); v.w = round_tf(v.w);
        ((float4*)dst)[i] = v;
    }
}

// ---------------- RoPE (writes tf32-rounded) ---------------------------------
__global__ void rope_q(const float* __restrict__ cosT, const float* __restrict__ sinT) {
    const int row = blockIdx.x;
    const int s = row & (SEQ - 1);
    const float* cr = cosT + (size_t)s * HD;
    const float* sr = sinT + (size_t)s * HD;
    float* base = g_q + (size_t)row * QLD;
    for (int idx = threadIdx.x; idx < NH * 64; idx += blockDim.x) {
        const int hh = idx >> 6, d = idx & 63;
        float* p = base + hh * HD;
        const float x1 = p[d], x2 = p[d + 64];
        p[d]      = round_tf(x1 * cr[d]      - x2 * sr[d]);
        p[d + 64] = round_tf(x2 * cr[d + 64] + x1 * sr[d + 64]);
    }
}
__global__ void rope_k(const float* __restrict__ cosT, const float* __restrict__ sinT) {
    const int row = blockIdx.x;
    const int s = row & (SEQ - 1);
    const float* cr = cosT + (size_t)s * HD;
    const float* sr = sinT + (size_t)s * HD;
    float* base = g_k + (size_t)row * KLD;
    for (int idx = threadIdx.x; idx < NKV * 64; idx += blockDim.x) {
        const int hh = idx >> 6, d = idx & 63;
        float* p = base + hh * HD;
        const float x1 = p[d], x2 = p[d + 64];
        p[d]      = round_tf(x1 * cr[d]      - x2 * sr[d]);
        p[d + 64] = round_tf(x2 * cr[d + 64] + x1 * sr[d + 64]);
    }
}

// ---------------- launch -----------------------------------------------------
extern "C" void kernel_launch(void* const* d_in, const int* in_sizes, int n_in,
                              void* d_out, int out_size) {
    (void)in_sizes; (void)n_in; (void)out_size;
    const float* hs   = (const float*)d_in[0];
    const float* Wq   = (const float*)d_in[1];
    const float* Wk   = (const float*)d_in[2];
    const float* Wv   = (const float*)d_in[3];
    const float* Wo   = (const float*)d_in[4];
    const float* cosT = (const float*)d_in[5];
    const float* sinT = (const float*)d_in[6];
    float* out = (float*)d_out;

    static bool attr_set = false;
    if (!attr_set) {
        cudaFuncSetAttribute(k_proj_q,   cudaFuncAttributeMaxDynamicSharedMemorySize, GSMEM);
        cudaFuncSetAttribute(k_proj_k,   cudaFuncAttributeMaxDynamicSharedMemorySize, GSMEM);
        cudaFuncSetAttribute(k_proj_v,   cudaFuncAttributeMaxDynamicSharedMemorySize, GSMEM);
        cudaFuncSetAttribute(k_out_proj, cudaFuncAttributeMaxDynamicSharedMemorySize, GSMEM);
        cudaFuncSetAttribute(k_flash,    cudaFuncAttributeMaxDynamicSharedMemorySize, FSMEM);
        attr_set = true;
    }

    float* phs;  cudaGetSymbolAddress((void**)&phs, g_hs);
    float* pwq;  cudaGetSymbolAddress((void**)&pwq, g_wq);
    float* pwk;  cudaGetSymbolAddress((void**)&pwk, g_wk);
    float* pwv;  cudaGetSymbolAddress((void**)&pwv, g_wv);
    float* pwo;  cudaGetSymbolAddress((void**)&pwo, g_wo);

    round_copy<<<1184, 256>>>(phs, hs, (int)((size_t)ROWS * HDIM / 4));
    round_copy<<<1184, 256>>>(pwq, Wq, (int)((size_t)QLD * HDIM / 4));
    round_copy<<<1184, 256>>>(pwk, Wk, (int)((size_t)KLD * HDIM / 4));
    round_copy<<<1184, 256>>>(pwv, Wv, (int)((size_t)KLD * HDIM / 4));
    round_copy<<<1184, 256>>>(pwo, Wo, (int)((size_t)HDIM * QLD / 4));

    k_proj_q<<<dim3(QLD / 128, ROWS / 128), 256, GSMEM>>>();
    k_proj_k<<<dim3(KLD / 128, ROWS / 128), 256, GSMEM>>>();
    k_proj_v<<<dim3(KLD / 128, ROWS / 128), 256, GSMEM>>>();
    rope_q<<<ROWS, 256>>>(cosT, sinT);
    rope_k<<<ROWS, 256>>>(cosT, sinT);
    k_flash<<<dim3(SEQ / 128, NBH), 256, FSMEM>>>();
    k_out_proj<<<dim3(HDIM / 128, ROWS / 128), 256, GSMEM>>>(out);
}